// round 2
// baseline (speedup 1.0000x reference)
#include <cuda_runtime.h>
#include <math.h>

#define NB 512
#define NN 128
#define CORR_LIM 2048
#define CAND_CAP (NB * 3 * NN)   // each row contributes at most 3 corr entries
#define EPS_W 1e-5

// ---------------- device scratch (no allocations allowed) ----------------
__device__ float        g_cand_val[CAND_CAP];
__device__ int          g_cand_idx[CAND_CAP];
__device__ int          g_cand_cnt;
__device__ unsigned int g_thresh;
__device__ int          g_G;
__device__ int          g_gt_ctr, g_eq_ctr;
__device__ float        g_localT[NB * 12];   // R row-major [0..8], t [9..11]
__device__ int          g_pc[NB];
__device__ int          g_counts[NB];
__device__ int          g_best;
__device__ float        g_sel_score[CORR_LIM];
__device__ float        g_sel_src[CORR_LIM * 3];
__device__ float        g_sel_ref[CORR_LIM * 3];
__device__ int          g_mtype[2];                 // 0=u8,1=i32,2=f32,3=bf16
__device__ unsigned char g_refm[NB * NN];
__device__ unsigned char g_srcm[NB * NN];

// ---------------- math helpers (double precision Kabsch) ----------------
__device__ inline double det3(const double* M) {
    return M[0]*(M[4]*M[8]-M[5]*M[7])
         - M[1]*(M[3]*M[8]-M[5]*M[6])
         + M[2]*(M[3]*M[7]-M[4]*M[6]);
}

__device__ void jacobi3(double A[9], double V[9]) {
    for (int i = 0; i < 9; i++) V[i] = (i % 4 == 0) ? 1.0 : 0.0;
    for (int sweep = 0; sweep < 20; sweep++) {
        double off = fabs(A[1]) + fabs(A[2]) + fabs(A[5]);
        if (off < 1e-30) break;
        for (int pq = 0; pq < 3; pq++) {
            int p = (pq == 2) ? 1 : 0;
            int q = (pq == 0) ? 1 : 2;
            double apq = A[p*3+q];
            if (fabs(apq) < 1e-300) continue;
            double theta = (A[q*3+q] - A[p*3+p]) / (2.0 * apq);
            double tt = ((theta >= 0.0) ? 1.0 : -1.0) / (fabs(theta) + sqrt(1.0 + theta*theta));
            double c = 1.0 / sqrt(1.0 + tt*tt);
            double s = tt * c;
            for (int k = 0; k < 3; k++) {
                double akp = A[k*3+p], akq = A[k*3+q];
                A[k*3+p] = c*akp - s*akq;
                A[k*3+q] = s*akp + c*akq;
            }
            for (int k = 0; k < 3; k++) {
                double apk = A[p*3+k], aqk = A[q*3+k];
                A[p*3+k] = c*apk - s*aqk;
                A[q*3+k] = s*apk + c*aqk;
            }
            for (int k = 0; k < 3; k++) {
                double vkp = V[k*3+p], vkq = V[k*3+q];
                V[k*3+p] = c*vkp - s*vkq;
                V[k*3+q] = s*vkp + c*vkq;
            }
        }
    }
}

// H[c*3+d] = sum w * src_c * ref_d  (centered). Returns proper rotation R with
// ref ~= R * src. Matches R = V E U^T with d = sign(det(V U^T)).
__device__ void kabsch(const double H[9], double R[9]) {
    double A[9];
    for (int i = 0; i < 3; i++)
        for (int j = 0; j < 3; j++)
            A[i*3+j] = H[0+i]*H[0+j] + H[3+i]*H[3+j] + H[6+i]*H[6+j]; // H^T H

    double V[9];
    jacobi3(A, V);
    double e0 = A[0], e1 = A[4], e2 = A[8];
    int o0 = 0, o1 = 1, o2 = 2;
    double t;
    int ti;
    if (e0 < e1) { t = e0; e0 = e1; e1 = t; ti = o0; o0 = o1; o1 = ti; }
    if (e0 < e2) { t = e0; e0 = e2; e2 = t; ti = o0; o0 = o2; o2 = ti; }
    if (e1 < e2) { t = e1; e1 = e2; e2 = t; ti = o1; o1 = o2; o2 = ti; }
    double Vs[9];
    int ord[3] = {o0, o1, o2};
    for (int r = 0; r < 3; r++)
        for (int k = 0; k < 3; k++)
            Vs[r*3+k] = V[r*3+ord[k]];

    // u_i = H v_i / s_i, with Gram-Schmidt + cross product (det U = +1)
    double u[3][3];
    for (int i = 0; i < 2; i++)
        for (int r = 0; r < 3; r++)
            u[i][r] = H[r*3+0]*Vs[0*3+i] + H[r*3+1]*Vs[1*3+i] + H[r*3+2]*Vs[2*3+i];
    double n0 = sqrt(u[0][0]*u[0][0] + u[0][1]*u[0][1] + u[0][2]*u[0][2]) + 1e-300;
    for (int r = 0; r < 3; r++) u[0][r] /= n0;
    double dp = u[1][0]*u[0][0] + u[1][1]*u[0][1] + u[1][2]*u[0][2];
    for (int r = 0; r < 3; r++) u[1][r] -= dp * u[0][r];
    double n1 = sqrt(u[1][0]*u[1][0] + u[1][1]*u[1][1] + u[1][2]*u[1][2]) + 1e-300;
    for (int r = 0; r < 3; r++) u[1][r] /= n1;
    u[2][0] = u[0][1]*u[1][2] - u[0][2]*u[1][1];
    u[2][1] = u[0][2]*u[1][0] - u[0][0]*u[1][2];
    u[2][2] = u[0][0]*u[1][1] - u[0][1]*u[1][0];

    double d = (det3(Vs) >= 0.0) ? 1.0 : -1.0;  // det U = +1 by construction
    double E[3] = {1.0, 1.0, d};
    for (int i = 0; i < 3; i++)
        for (int j = 0; j < 3; j++)
            R[i*3+j] = Vs[i*3+0]*E[0]*u[0][j] + Vs[i*3+1]*E[1]*u[1][j] + Vs[i*3+2]*E[2]*u[2][j];
}

// P: [0]=Sum w, [1..3]=Sum w*s, [4..6]=Sum w*r, [7..15]=Sum w*s_c*r_d (c*3+d)
__device__ void solveT(const double* P, double R[9], double tv[3]) {
    double denom = P[0] + EPS_W;
    double sc[3] = {P[1]/denom, P[2]/denom, P[3]/denom};
    double rc[3] = {P[4]/denom, P[5]/denom, P[6]/denom};
    double W = P[0] / denom;
    double H[9];
    for (int c = 0; c < 3; c++)
        for (int d = 0; d < 3; d++)
            H[c*3+d] = P[7 + c*3 + d] / denom + (W - 2.0) * sc[c] * rc[d];
    kabsch(H, R);
    for (int i = 0; i < 3; i++)
        tv[i] = rc[i] - (R[i*3+0]*sc[0] + R[i*3+1]*sc[1] + R[i*3+2]*sc[2]);
}

// ---------------- mask dtype detection + normalization ----------------
// Classify byte pattern of a boolean-ish array of 65536 elements:
//   u8/bool: 0x01 bytes at all offsets (incl. odd)
//   i32:     0x01 only at offsets % 4 == 0
//   f32:     1.0f = 00 00 80 3F -> 0x3F at offsets % 4 == 3
//   bf16:    1.0  = 80 3F       -> 0x3F at offsets % 4 == 1 (and 3)
__global__ void k_detect(const unsigned char* m0, const unsigned char* m1) {
    __shared__ int c3F_3, c3F_1, c01_1;
    const unsigned char* p = (blockIdx.x == 0) ? m0 : m1;
    int t = threadIdx.x;
    if (t == 0) { c3F_3 = 0; c3F_1 = 0; c01_1 = 0; }
    __syncthreads();
    int l3 = 0, l1 = 0, o1 = 0;
    for (int i = t; i < 4096; i += 256) {
        unsigned char b = p[i];
        int m = i & 3;
        if (b == 0x3F) { if (m == 3) l3++; else if (m == 1) l1++; }
        if (b == 0x01 && m == 1) o1++;
    }
    if (l3) atomicAdd(&c3F_3, l3);
    if (l1) atomicAdd(&c3F_1, l1);
    if (o1) atomicAdd(&c01_1, o1);
    __syncthreads();
    if (t == 0) {
        int ty;
        if (c3F_1 > 32)      ty = 3;   // bf16
        else if (c3F_3 > 32) ty = 2;   // f32
        else if (c01_1 > 32) ty = 0;   // u8 / bool
        else                 ty = 1;   // i32
        g_mtype[blockIdx.x] = ty;
    }
}

__device__ inline unsigned char fetch_mask(const void* p, int i, int ty) {
    switch (ty) {
        case 0:  return ((const unsigned char*)p)[i] != 0;
        case 1:  return ((const int*)p)[i] != 0;
        case 2:  return ((const unsigned int*)p)[i] != 0;
        default: return ((const unsigned short*)p)[i] != 0;
    }
}

__global__ void k_normmask(const void* m0, const void* m1) {
    int i = blockIdx.x * blockDim.x + threadIdx.x;
    if (i >= NB * NN) return;
    g_refm[i] = fetch_mask(m0, i, g_mtype[0]);
    g_srcm[i] = fetch_mask(m1, i, g_mtype[1]);
}

// ---------------- kernels ----------------
__global__ void k_init() {
    int i = blockIdx.x * blockDim.x + threadIdx.x;
    if (i < CORR_LIM) g_sel_score[i] = 0.0f;
    if (i == 0) {
        g_cand_cnt = 0; g_gt_ctr = 0; g_eq_ctr = 0;
        g_thresh = 0;   g_G = 0;      g_best = 0;
    }
}

// one CTA per batch: exp / top-3 / corr / moments / Kabsch + candidate compaction
__global__ void __launch_bounds__(128)
k1_batch(const float* __restrict__ score,
         const float* __restrict__ refp,
         const float* __restrict__ srcp)
{
    extern __shared__ float sm[];
    float* S    = sm;                                  // [128*129] stride-129: conflict-free
    float* col3 = sm + 16512;                          // [128]
    float* srcP = sm + 16640;                          // [384]
    float* refP = sm + 17024;                          // [384]
    unsigned char* smask = (unsigned char*)(sm + 17408); // [128]

    int b = blockIdx.x;
    int t = threadIdx.x;
    const float* sb = score + (size_t)b * (NN * NN);

    for (int i = t; i < NN * NN; i += 128)
        S[(i >> 7) * 129 + (i & 127)] = sb[i];
    for (int i = t; i < 384; i += 128) {
        srcP[i] = srcp[b * 384 + i];
        refP[i] = refp[b * 384 + i];
    }
    smask[t] = g_srcm[b * NN + t];
    __syncthreads();

    // row top-3 threshold (3rd largest raw score; monotonic with exp)
    float a1 = -3e38f, a2 = -3e38f, a3 = -3e38f;
    const float* row = S + t * 129;
    for (int s = 0; s < NN; s++) {
        float v = row[s];
        if (v > a1)      { a3 = a2; a2 = a1; a1 = v; }
        else if (v > a2) { a3 = a2; a2 = v; }
        else if (v > a3) { a3 = v; }
    }
    float rowth = a3;
    // column top-3 threshold
    float c1 = -3e38f, c2 = -3e38f, c3 = -3e38f;
    for (int r = 0; r < NN; r++) {
        float v = S[r * 129 + t];
        if (v > c1)      { c3 = c2; c2 = c1; c1 = v; }
        else if (v > c2) { c3 = c2; c2 = v; }
        else if (v > c3) { c3 = v; }
    }
    col3[t] = c3;
    __syncthreads();

    unsigned char rm = g_refm[b * NN + t];
    double P[16];
    for (int j = 0; j < 16; j++) P[j] = 0.0;
    int cnt = 0;
    float rfx = refP[t*3+0], rfy = refP[t*3+1], rfz = refP[t*3+2];

    if (rm) {
        for (int s = 0; s < NN; s++) {
            float v = row[s];
            if (v < rowth || v < col3[s]) continue;   // must be row-top3 AND col-top3
            if (!smask[s]) continue;
            float e = expf(v);
            if (!(e > 0.05f)) continue;
            double w = (double)e;
            P[0] += w;
            P[1] += w * (double)srcP[s*3+0];
            P[2] += w * (double)srcP[s*3+1];
            P[3] += w * (double)srcP[s*3+2];
            cnt++;
            int pos = atomicAdd(&g_cand_cnt, 1);
            if (pos < CAND_CAP) {
                g_cand_val[pos] = e;
                g_cand_idx[pos] = (b << 14) | (t << 7) | s;
            }
        }
        P[4] = P[0] * rfx;  P[5] = P[0] * rfy;  P[6] = P[0] * rfz;
        P[7]  = P[1]*rfx; P[8]  = P[1]*rfy; P[9]  = P[1]*rfz;
        P[10] = P[2]*rfx; P[11] = P[2]*rfy; P[12] = P[2]*rfz;
        P[13] = P[3]*rfx; P[14] = P[3]*rfy; P[15] = P[3]*rfz;
    }
    __syncthreads();

    // block reduce (overlay the score region — scores no longer needed)
    double* red = (double*)sm;
    int* redi = (int*)(red + 128 * 16);
    for (int j = 0; j < 16; j++) red[t*16+j] = P[j];
    redi[t] = cnt;
    __syncthreads();
    for (int off = 64; off; off >>= 1) {
        if (t < off) {
            for (int j = 0; j < 16; j++) red[t*16+j] += red[(t+off)*16+j];
            redi[t] += redi[t + off];
        }
        __syncthreads();
    }

    if (t == 0) {
        double R[9], tv[3];
        solveT(red, R, tv);
        for (int j = 0; j < 9; j++) g_localT[b*12+j]     = (float)R[j];
        for (int j = 0; j < 3; j++) g_localT[b*12+9+j]   = (float)tv[j];
        g_pc[b] = redi[0];
    }
}

// exact radix-select of the 2048th-largest candidate value (positive floats)
__global__ void __launch_bounds__(1024)
k2_select()
{
    __shared__ unsigned int hist[256];
    __shared__ unsigned int s_prefix, s_k;
    __shared__ int gs[1024];
    int tid = threadIdx.x;
    int M = g_cand_cnt;
    if (M > CAND_CAP) M = CAND_CAP;

    if (M <= CORR_LIM) {
        if (tid == 0) { g_thresh = 0u; g_G = 0; }
        return;
    }
    if (tid == 0) { s_prefix = 0u; s_k = CORR_LIM; }
    __syncthreads();

    for (int byte = 3; byte >= 0; byte--) {
        if (tid < 256) hist[tid] = 0u;
        __syncthreads();
        unsigned int pf = s_prefix;
        unsigned int mask = (byte == 3) ? 0u : (0xFFFFFFFFu << ((byte + 1) * 8));
        for (int i = tid; i < M; i += 1024) {
            unsigned int v = __float_as_uint(g_cand_val[i]);
            if ((v & mask) == pf) atomicAdd(&hist[(v >> (byte * 8)) & 255u], 1u);
        }
        __syncthreads();
        if (tid == 0) {
            unsigned int k = s_k, run = 0u;
            int d = 255;
            for (; d >= 0; d--) {
                if (run + hist[d] >= k) break;
                run += hist[d];
            }
            if (d < 0) d = 0;
            s_prefix = pf | ((unsigned int)d << (byte * 8));
            s_k = k - run;
        }
        __syncthreads();
    }

    unsigned int th = s_prefix;
    int g = 0;
    for (int i = tid; i < M; i += 1024)
        if (__float_as_uint(g_cand_val[i]) > th) g++;
    gs[tid] = g;
    __syncthreads();
    for (int off = 512; off; off >>= 1) {
        if (tid < off) gs[tid] += gs[tid + off];
        __syncthreads();
    }
    if (tid == 0) { g_thresh = th; g_G = gs[0]; }
}

// gather the top-2048 entries: score + corresponding src/ref points
__global__ void __launch_bounds__(256)
k3_gather(const float* __restrict__ refp, const float* __restrict__ srcp)
{
    int M = g_cand_cnt;
    if (M > CAND_CAP) M = CAND_CAP;
    int i = blockIdx.x * blockDim.x + threadIdx.x;
    if (i >= M) return;
    float v = g_cand_val[i];
    unsigned int bits = __float_as_uint(v);
    unsigned int th = g_thresh;
    int slot = -1;
    if (bits > th) {
        slot = atomicAdd(&g_gt_ctr, 1);
    } else if (bits == th) {
        int e = atomicAdd(&g_eq_ctr, 1);
        int p = g_G + e;
        if (p < CORR_LIM) slot = p;
    }
    if (slot >= 0 && slot < CORR_LIM) {
        int idx = g_cand_idx[i];
        int b = idx >> 14, r = (idx >> 7) & 127, s = idx & 127;
        g_sel_score[slot] = v;
        g_sel_src[slot*3+0] = srcp[(b*NN + s)*3 + 0];
        g_sel_src[slot*3+1] = srcp[(b*NN + s)*3 + 1];
        g_sel_src[slot*3+2] = srcp[(b*NN + s)*3 + 2];
        g_sel_ref[slot*3+0] = refp[(b*NN + r)*3 + 0];
        g_sel_ref[slot*3+1] = refp[(b*NN + r)*3 + 1];
        g_sel_ref[slot*3+2] = refp[(b*NN + r)*3 + 2];
    }
}

// inlier counts per local transform
__global__ void __launch_bounds__(256)
k4_counts()
{
    __shared__ int rc_[256];
    int p = blockIdx.x, t = threadIdx.x;
    const float* LT = &g_localT[p * 12];
    float R0 = LT[0], R1 = LT[1], R2 = LT[2];
    float R3 = LT[3], R4 = LT[4], R5 = LT[5];
    float R6 = LT[6], R7 = LT[7], R8 = LT[8];
    float t0 = LT[9], t1 = LT[10], t2 = LT[11];
    int c = 0;
    for (int i = t; i < CORR_LIM; i += 256) {
        float sv = g_sel_score[i];
        if (sv <= 0.0f) continue;   // valid mask
        float sx = g_sel_src[i*3+0], sy = g_sel_src[i*3+1], sz = g_sel_src[i*3+2];
        float rx = g_sel_ref[i*3+0], ry = g_sel_ref[i*3+1], rz = g_sel_ref[i*3+2];
        float ax = R0*sx + R1*sy + R2*sz + t0;
        float ay = R3*sx + R4*sy + R5*sz + t1;
        float az = R6*sx + R7*sy + R8*sz + t2;
        float dx = rx - ax, dy = ry - ay, dz = rz - az;
        if (dx*dx + dy*dy + dz*dz < 0.01f) c++;
    }
    rc_[t] = c;
    __syncthreads();
    for (int off = 128; off; off >>= 1) {
        if (t < off) rc_[t] += rc_[t + off];
        __syncthreads();
    }
    if (t == 0) g_counts[p] = (g_pc[p] >= 3) ? rc_[0] : -1;
}

// argmax (first occurrence of max, i.e. tie -> smaller index)
__global__ void __launch_bounds__(512)
k4_argmax()
{
    __shared__ int sc_[512], si_[512];
    int t = threadIdx.x;
    sc_[t] = g_counts[t];
    si_[t] = t;
    __syncthreads();
    for (int off = 256; off; off >>= 1) {
        if (t < off) {
            int c2 = sc_[t + off], i2 = si_[t + off];
            if (c2 > sc_[t] || (c2 == sc_[t] && i2 < si_[t])) { sc_[t] = c2; si_[t] = i2; }
        }
        __syncthreads();
    }
    if (t == 0) g_best = si_[0];
}

// 5 weighted-Procrustes iterations on the 2048 selected correspondences
__global__ void __launch_bounds__(256)
k5_refine(float* __restrict__ out)
{
    __shared__ double red[256 * 16];
    __shared__ double Tr[9], Tt[3];
    int t = threadIdx.x;
    if (t == 0) {
        int bb = g_best;
        for (int j = 0; j < 9; j++) Tr[j] = (double)g_localT[bb*12+j];
        for (int j = 0; j < 3; j++) Tt[j] = (double)g_localT[bb*12+9+j];
    }
    __syncthreads();

    for (int it = 0; it < 5; it++) {
        double P[16];
        for (int j = 0; j < 16; j++) P[j] = 0.0;
        for (int i = t; i < CORR_LIM; i += 256) {
            float sv = g_sel_score[i];
            if (sv <= 0.0f) continue;
            double sx = g_sel_src[i*3+0], sy = g_sel_src[i*3+1], sz = g_sel_src[i*3+2];
            double rx = g_sel_ref[i*3+0], ry = g_sel_ref[i*3+1], rz = g_sel_ref[i*3+2];
            double ax = Tr[0]*sx + Tr[1]*sy + Tr[2]*sz + Tt[0];
            double ay = Tr[3]*sx + Tr[4]*sy + Tr[5]*sz + Tt[1];
            double az = Tr[6]*sx + Tr[7]*sy + Tr[8]*sz + Tt[2];
            double dx = rx - ax, dy = ry - ay, dz = rz - az;
            if (dx*dx + dy*dy + dz*dz < 0.01) {
                double w = (double)sv;
                P[0] += w;
                P[1] += w*sx; P[2] += w*sy; P[3] += w*sz;
                P[4] += w*rx; P[5] += w*ry; P[6] += w*rz;
                P[7]  += w*sx*rx; P[8]  += w*sx*ry; P[9]  += w*sx*rz;
                P[10] += w*sy*rx; P[11] += w*sy*ry; P[12] += w*sy*rz;
                P[13] += w*sz*rx; P[14] += w*sz*ry; P[15] += w*sz*rz;
            }
        }
        for (int j = 0; j < 16; j++) red[t*16+j] = P[j];
        __syncthreads();
        for (int off = 128; off; off >>= 1) {
            if (t < off)
                for (int j = 0; j < 16; j++) red[t*16+j] += red[(t+off)*16+j];
            __syncthreads();
        }
        if (t == 0) {
            double R[9], tv[3];
            solveT(red, R, tv);
            for (int j = 0; j < 9; j++) Tr[j] = R[j];
            for (int j = 0; j < 3; j++) Tt[j] = tv[j];
        }
        __syncthreads();
    }

    if (t == 0) {
        out[0]  = (float)Tr[0]; out[1]  = (float)Tr[1]; out[2]  = (float)Tr[2]; out[3]  = (float)Tt[0];
        out[4]  = (float)Tr[3]; out[5]  = (float)Tr[4]; out[6]  = (float)Tr[5]; out[7]  = (float)Tt[1];
        out[8]  = (float)Tr[6]; out[9]  = (float)Tr[7]; out[10] = (float)Tr[8]; out[11] = (float)Tt[2];
        out[12] = 0.0f; out[13] = 0.0f; out[14] = 0.0f; out[15] = 1.0f;
    }
}

// ---------------- launch ----------------
extern "C" void kernel_launch(void* const* d_in, const int* in_sizes, int n_in,
                              void* d_out, int out_size)
{
    // Route inputs by element count (robust to metadata ordering):
    //   8388608 -> score_mat; 196608 -> points (ref first, then src);
    //   65536   -> masks (ref first, then src).
    const float* score = 0;
    const float* refp = 0;  const float* srcp = 0;
    const void*  refm = 0;  const void*  srcm = 0;
    for (int i = 0; i < n_in; i++) {
        int sz = in_sizes[i];
        if (sz == NB * NN * NN) {
            score = (const float*)d_in[i];
        } else if (sz == NB * NN * 3) {
            if (!refp) refp = (const float*)d_in[i];
            else       srcp = (const float*)d_in[i];
        } else if (sz == NB * NN) {
            if (!refm) refm = d_in[i];
            else       srcm = d_in[i];
        }
    }
    float* out = (float*)d_out;

    const int k1_smem = 16512*4 + 128*4 + 768*4 + 128; // 69760 bytes
    cudaFuncSetAttribute(k1_batch, cudaFuncAttributeMaxDynamicSharedMemorySize, k1_smem);

    k_detect<<<2, 256>>>((const unsigned char*)refm, (const unsigned char*)srcm);
    k_normmask<<<(NB * NN + 255) / 256, 256>>>(refm, srcm);
    k_init<<<(CORR_LIM + 255) / 256, 256>>>();
    k1_batch<<<NB, 128, k1_smem>>>(score, refp, srcp);
    k2_select<<<1, 1024>>>();
    k3_gather<<<(CAND_CAP + 255) / 256, 256>>>(refp, srcp);
    k4_counts<<<NB, 256>>>();
    k4_argmax<<<1, 512>>>();
    k5_refine<<<1, 256>>>(out);
}

// round 3
// speedup vs baseline: 3.0898x; 3.0898x over previous
#include <cuda_runtime.h>
#include <math.h>

#define NB 512
#define NN 128
#define CORR_LIM 2048
#define CAND_CAP (NB * 3 * NN)
#define NEG_INF -3e38f

// ---------------- device scratch ----------------
__device__ float        g_cand_val[CAND_CAP];
__device__ int          g_cand_idx[CAND_CAP];
__device__ int          g_cand_cnt;
__device__ unsigned int g_thresh;
__device__ int          g_G;
__device__ int          g_gt_ctr, g_eq_ctr;
__device__ float        g_localT[NB * 12];
__device__ int          g_pc[NB];
__device__ int          g_best_key;
__device__ float        g_sel_score[CORR_LIM];
__device__ float        g_sel_src[CORR_LIM * 3];
__device__ float        g_sel_ref[CORR_LIM * 3];
__device__ int          g_mtype[2];
__device__ unsigned char g_refm[NB * NN];
__device__ unsigned char g_srcm[NB * NN];

// ---------------- f32 Kabsch ----------------
__device__ inline float det3f(const float* M) {
    return M[0]*(M[4]*M[8]-M[5]*M[7])
         - M[1]*(M[3]*M[8]-M[5]*M[6])
         + M[2]*(M[3]*M[7]-M[4]*M[6]);
}

__device__ void jacobi3f(float A[9], float V[9]) {
    for (int i = 0; i < 9; i++) V[i] = (i % 4 == 0) ? 1.0f : 0.0f;
    float fro = fabsf(A[0]) + fabsf(A[4]) + fabsf(A[8]) + 1e-30f;
    for (int sweep = 0; sweep < 10; sweep++) {
        float off = fabsf(A[1]) + fabsf(A[2]) + fabsf(A[5]);
        if (off < fro * 1e-7f + 1e-35f) break;
        for (int pq = 0; pq < 3; pq++) {
            int p = (pq == 2) ? 1 : 0;
            int q = (pq == 0) ? 1 : 2;
            float apq = A[p*3+q];
            if (fabsf(apq) < 1e-35f) continue;
            float theta = (A[q*3+q] - A[p*3+p]) / (2.0f * apq);
            float tt = ((theta >= 0.0f) ? 1.0f : -1.0f) / (fabsf(theta) + sqrtf(1.0f + theta*theta));
            float c = rsqrtf(1.0f + tt*tt);
            float s = tt * c;
            for (int k = 0; k < 3; k++) {
                float akp = A[k*3+p], akq = A[k*3+q];
                A[k*3+p] = c*akp - s*akq;
                A[k*3+q] = s*akp + c*akq;
            }
            for (int k = 0; k < 3; k++) {
                float apk = A[p*3+k], aqk = A[q*3+k];
                A[p*3+k] = c*apk - s*aqk;
                A[q*3+k] = s*apk + c*aqk;
            }
            for (int k = 0; k < 3; k++) {
                float vkp = V[k*3+p], vkq = V[k*3+q];
                V[k*3+p] = c*vkp - s*vkq;
                V[k*3+q] = s*vkp + c*vkq;
            }
        }
    }
}

__device__ void kabschf(const float H[9], float R[9]) {
    float A[9];
    for (int i = 0; i < 3; i++)
        for (int j = 0; j < 3; j++)
            A[i*3+j] = H[0+i]*H[0+j] + H[3+i]*H[3+j] + H[6+i]*H[6+j];

    float V[9];
    jacobi3f(A, V);
    float e0 = A[0], e1 = A[4], e2 = A[8];
    int o0 = 0, o1 = 1, o2 = 2;
    float t; int ti;
    if (e0 < e1) { t = e0; e0 = e1; e1 = t; ti = o0; o0 = o1; o1 = ti; }
    if (e0 < e2) { t = e0; e0 = e2; e2 = t; ti = o0; o0 = o2; o2 = ti; }
    if (e1 < e2) { t = e1; e1 = e2; e2 = t; ti = o1; o1 = o2; o2 = ti; }
    float Vs[9];
    int ord[3] = {o0, o1, o2};
    for (int r = 0; r < 3; r++)
        for (int k = 0; k < 3; k++)
            Vs[r*3+k] = V[r*3+ord[k]];

    float u[3][3];
    for (int i = 0; i < 2; i++)
        for (int r = 0; r < 3; r++)
            u[i][r] = H[r*3+0]*Vs[0*3+i] + H[r*3+1]*Vs[1*3+i] + H[r*3+2]*Vs[2*3+i];
    float n0 = sqrtf(u[0][0]*u[0][0] + u[0][1]*u[0][1] + u[0][2]*u[0][2]) + 1e-30f;
    for (int r = 0; r < 3; r++) u[0][r] /= n0;
    float dp = u[1][0]*u[0][0] + u[1][1]*u[0][1] + u[1][2]*u[0][2];
    for (int r = 0; r < 3; r++) u[1][r] -= dp * u[0][r];
    float n1 = sqrtf(u[1][0]*u[1][0] + u[1][1]*u[1][1] + u[1][2]*u[1][2]) + 1e-30f;
    for (int r = 0; r < 3; r++) u[1][r] /= n1;
    u[2][0] = u[0][1]*u[1][2] - u[0][2]*u[1][1];
    u[2][1] = u[0][2]*u[1][0] - u[0][0]*u[1][2];
    u[2][2] = u[0][0]*u[1][1] - u[0][1]*u[1][0];

    float d = (det3f(Vs) >= 0.0f) ? 1.0f : -1.0f;
    float E2 = d;
    for (int i = 0; i < 3; i++)
        for (int j = 0; j < 3; j++)
            R[i*3+j] = Vs[i*3+0]*u[0][j] + Vs[i*3+1]*u[1][j] + Vs[i*3+2]*E2*u[2][j];
}

// P: [0]=Sw, [1..3]=Sw*s, [4..6]=Sw*r, [7..15]=Sw*s_c*r_d
__device__ void solveTf(const float* P, float R[9], float tv[3]) {
    float denom = P[0] + 1e-5f;
    float sc[3] = {P[1]/denom, P[2]/denom, P[3]/denom};
    float rc[3] = {P[4]/denom, P[5]/denom, P[6]/denom};
    float W = P[0] / denom;
    float H[9];
    for (int c = 0; c < 3; c++)
        for (int d = 0; d < 3; d++)
            H[c*3+d] = P[7 + c*3 + d] / denom + (W - 2.0f) * sc[c] * rc[d];
    kabschf(H, R);
    for (int i = 0; i < 3; i++)
        tv[i] = rc[i] - (R[i*3+0]*sc[0] + R[i*3+1]*sc[1] + R[i*3+2]*sc[2]);
}

// ---------------- mask dtype detection + normalization ----------------
__global__ void k_detect(const unsigned char* m0, const unsigned char* m1) {
    __shared__ int c3F_3, c3F_1, c01_1;
    const unsigned char* p = (blockIdx.x == 0) ? m0 : m1;
    int t = threadIdx.x;
    if (t == 0) { c3F_3 = 0; c3F_1 = 0; c01_1 = 0; }
    __syncthreads();
    int l3 = 0, l1 = 0, o1 = 0;
    for (int i = t; i < 4096; i += 256) {
        unsigned char bch = p[i];
        int m = i & 3;
        if (bch == 0x3F) { if (m == 3) l3++; else if (m == 1) l1++; }
        if (bch == 0x01 && m == 1) o1++;
    }
    if (l3) atomicAdd(&c3F_3, l3);
    if (l1) atomicAdd(&c3F_1, l1);
    if (o1) atomicAdd(&c01_1, o1);
    __syncthreads();
    if (t == 0) {
        int ty;
        if (c3F_1 > 32)      ty = 3;
        else if (c3F_3 > 32) ty = 2;
        else if (c01_1 > 32) ty = 0;
        else                 ty = 1;
        g_mtype[blockIdx.x] = ty;
    }
}

__device__ inline unsigned char fetch_mask(const void* p, int i, int ty) {
    switch (ty) {
        case 0:  return ((const unsigned char*)p)[i] != 0;
        case 1:  return ((const int*)p)[i] != 0;
        case 2:  return ((const unsigned int*)p)[i] != 0;
        default: return ((const unsigned short*)p)[i] != 0;
    }
}

__global__ void k_norm_init(const void* m0, const void* m1) {
    int i = blockIdx.x * blockDim.x + threadIdx.x;
    if (i < CORR_LIM) g_sel_score[i] = 0.0f;
    if (i == 0) {
        g_cand_cnt = 0; g_gt_ctr = 0; g_eq_ctr = 0;
        g_thresh = 0;   g_G = 0;      g_best_key = 0;
    }
    if (i < NB * NN) {
        g_refm[i] = fetch_mask(m0, i, g_mtype[0]);
        g_srcm[i] = fetch_mask(m1, i, g_mtype[1]);
    }
}

// insert one value into a sorted top-3 triple
#define INS3(a1, a2, a3, vv) { float _v = (vv); \
    if (_v > a1)      { a3 = a2; a2 = a1; a1 = _v; } \
    else if (_v > a2) { a3 = a2; a2 = _v; } \
    else if (_v > a3) { a3 = _v; } }

// ---------------- k1: per-batch top3 / candidates / moments / Kabsch ------
__global__ void __launch_bounds__(256)
k1_batch(const float* __restrict__ score,
         const float* __restrict__ refp,
         const float* __restrict__ srcp)
{
    __shared__ float rowth[NN], colth[NN];
    __shared__ float chA[NN][3];
    __shared__ unsigned char s_srcm[NN], s_refm[NN];
    __shared__ float sP[16];
    __shared__ int   scnt;

    int b = blockIdx.x, t = threadIdx.x;
    const float* Sb = score + (size_t)b * (NN * NN);

    if (t < 16) sP[t] = 0.0f;
    if (t == 0) scnt = 0;
    if (t < NN) { s_srcm[t] = g_srcm[b*NN + t]; s_refm[t] = g_refm[b*NN + t]; }

    // --- pass A: column top-3, thread-per-(column,half), coalesced global reads
    int s = t & 127, h = t >> 7;
    float c1 = NEG_INF, c2 = NEG_INF, c3 = NEG_INF;
    {
        const float* colp = Sb + s + (h * 64) * NN;
        #pragma unroll 4
        for (int r = 0; r < 64; r++) {
            float v = colp[r * NN];
            INS3(c1, c2, c3, v);
        }
    }
    if (h) { chA[s][0] = c1; chA[s][1] = c2; chA[s][2] = c3; }

    // --- pass B: row top-3, warp per 16 rows, float4 + xor-butterfly merge
    int w = t >> 5, lane = t & 31;
    for (int i = 0; i < 16; i++) {
        int r = (w << 4) + i;
        float4 v4 = *(const float4*)(Sb + r * NN + lane * 4);
        float a1 = v4.x, a2 = NEG_INF, a3 = NEG_INF;
        INS3(a1, a2, a3, v4.y);
        INS3(a1, a2, a3, v4.z);
        INS3(a1, a2, a3, v4.w);
        #pragma unroll
        for (int off = 16; off; off >>= 1) {
            float b1 = __shfl_xor_sync(0xffffffffu, a1, off);
            float b2 = __shfl_xor_sync(0xffffffffu, a2, off);
            float b3 = __shfl_xor_sync(0xffffffffu, a3, off);
            INS3(a1, a2, a3, b1);
            INS3(a1, a2, a3, b2);
            INS3(a1, a2, a3, b3);
        }
        if (lane == 0) rowth[r] = a3;
    }
    __syncthreads();

    // --- merge column halves
    if (!h) {
        INS3(c1, c2, c3, chA[s][0]);
        INS3(c1, c2, c3, chA[s][1]);
        INS3(c1, c2, c3, chA[s][2]);
        colth[s] = c3;
    }
    __syncthreads();

    // --- pass C: candidates + moments (warp per 16 rows, re-read via L2)
    for (int i = 0; i < 16; i++) {
        int r = (w << 4) + i;
        if (!s_refm[r]) continue;
        float rth = rowth[r];
        float4 v4 = *(const float4*)(Sb + r * NN + lane * 4);
        float vv[4] = {v4.x, v4.y, v4.z, v4.w};
        #pragma unroll
        for (int j = 0; j < 4; j++) {
            float v = vv[j];
            int ss = lane * 4 + j;
            if (v < rth || v < colth[ss] || !s_srcm[ss]) continue;
            float e = expf(v);
            if (!(e > 0.05f)) continue;
            int pos = atomicAdd(&g_cand_cnt, 1);
            g_cand_val[pos] = e;
            g_cand_idx[pos] = (b << 14) | (r << 7) | ss;
            float sx = srcp[(b*NN + ss)*3 + 0];
            float sy = srcp[(b*NN + ss)*3 + 1];
            float sz = srcp[(b*NN + ss)*3 + 2];
            float rx = refp[(b*NN + r)*3 + 0];
            float ry = refp[(b*NN + r)*3 + 1];
            float rz = refp[(b*NN + r)*3 + 2];
            atomicAdd(&scnt, 1);
            atomicAdd(&sP[0], e);
            atomicAdd(&sP[1], e*sx);  atomicAdd(&sP[2], e*sy);  atomicAdd(&sP[3], e*sz);
            atomicAdd(&sP[4], e*rx);  atomicAdd(&sP[5], e*ry);  atomicAdd(&sP[6], e*rz);
            atomicAdd(&sP[7],  e*sx*rx); atomicAdd(&sP[8],  e*sx*ry); atomicAdd(&sP[9],  e*sx*rz);
            atomicAdd(&sP[10], e*sy*rx); atomicAdd(&sP[11], e*sy*ry); atomicAdd(&sP[12], e*sy*rz);
            atomicAdd(&sP[13], e*sz*rx); atomicAdd(&sP[14], e*sz*ry); atomicAdd(&sP[15], e*sz*rz);
        }
    }
    __syncthreads();

    if (t == 0) {
        float P[16];
        for (int j = 0; j < 16; j++) P[j] = sP[j];
        float R[9], tv[3];
        solveTf(P, R, tv);
        for (int j = 0; j < 9; j++) g_localT[b*12 + j] = R[j];
        for (int j = 0; j < 3; j++) g_localT[b*12 + 9 + j] = tv[j];
        g_pc[b] = scnt;
    }
}

// ---------------- k2: exact radix-select of 2048th-largest ----------------
__global__ void __launch_bounds__(1024)
k2_select()
{
    __shared__ unsigned int hist[256];
    __shared__ unsigned int s_prefix, s_k;
    __shared__ int gs[1024];
    int tid = threadIdx.x;
    int M = g_cand_cnt;
    if (M > CAND_CAP) M = CAND_CAP;

    if (M <= CORR_LIM) {
        if (tid == 0) { g_thresh = 0u; g_G = 0; }
        return;
    }
    if (tid == 0) { s_prefix = 0u; s_k = CORR_LIM; }
    __syncthreads();

    for (int byte = 3; byte >= 0; byte--) {
        if (tid < 256) hist[tid] = 0u;
        __syncthreads();
        unsigned int pf = s_prefix;
        unsigned int mask = (byte == 3) ? 0u : (0xFFFFFFFFu << ((byte + 1) * 8));
        for (int i = tid; i < M; i += 1024) {
            unsigned int v = __float_as_uint(g_cand_val[i]);
            if ((v & mask) == pf) atomicAdd(&hist[(v >> (byte * 8)) & 255u], 1u);
        }
        __syncthreads();
        if (tid == 0) {
            unsigned int k = s_k, run = 0u;
            int d = 255;
            for (; d >= 0; d--) {
                if (run + hist[d] >= k) break;
                run += hist[d];
            }
            if (d < 0) d = 0;
            s_prefix = pf | ((unsigned int)d << (byte * 8));
            s_k = k - run;
        }
        __syncthreads();
    }

    unsigned int th = s_prefix;
    int g = 0;
    for (int i = tid; i < M; i += 1024)
        if (__float_as_uint(g_cand_val[i]) > th) g++;
    gs[tid] = g;
    __syncthreads();
    for (int off = 512; off; off >>= 1) {
        if (tid < off) gs[tid] += gs[tid + off];
        __syncthreads();
    }
    if (tid == 0) { g_thresh = th; g_G = gs[0]; }
}

// ---------------- k3: gather top-2048 ----------------
__global__ void __launch_bounds__(256)
k3_gather(const float* __restrict__ refp, const float* __restrict__ srcp)
{
    int M = g_cand_cnt;
    if (M > CAND_CAP) M = CAND_CAP;
    int i = blockIdx.x * blockDim.x + threadIdx.x;
    if (i >= M) return;
    float v = g_cand_val[i];
    unsigned int bits = __float_as_uint(v);
    unsigned int th = g_thresh;
    int slot = -1;
    if (bits > th) {
        slot = atomicAdd(&g_gt_ctr, 1);
    } else if (bits == th) {
        int e = atomicAdd(&g_eq_ctr, 1);
        int p = g_G + e;
        if (p < CORR_LIM) slot = p;
    }
    if (slot >= 0 && slot < CORR_LIM) {
        int idx = g_cand_idx[i];
        int b = idx >> 14, r = (idx >> 7) & 127, s = idx & 127;
        g_sel_score[slot] = v;
        g_sel_src[slot*3+0] = srcp[(b*NN + s)*3 + 0];
        g_sel_src[slot*3+1] = srcp[(b*NN + s)*3 + 1];
        g_sel_src[slot*3+2] = srcp[(b*NN + s)*3 + 2];
        g_sel_ref[slot*3+0] = refp[(b*NN + r)*3 + 0];
        g_sel_ref[slot*3+1] = refp[(b*NN + r)*3 + 1];
        g_sel_ref[slot*3+2] = refp[(b*NN + r)*3 + 2];
    }
}

// ---------------- k4: inlier counts + packed argmax ----------------
__global__ void __launch_bounds__(128)
k4_counts()
{
    __shared__ int rc_[128];
    int p = blockIdx.x, t = threadIdx.x;
    const float* LT = &g_localT[p * 12];
    float R0 = LT[0], R1 = LT[1], R2 = LT[2];
    float R3 = LT[3], R4 = LT[4], R5 = LT[5];
    float R6 = LT[6], R7 = LT[7], R8 = LT[8];
    float t0 = LT[9], t1 = LT[10], t2 = LT[11];
    int c = 0;
    for (int i = t; i < CORR_LIM; i += 128) {
        float sv = g_sel_score[i];
        if (sv <= 0.0f) continue;
        float sx = g_sel_src[i*3+0], sy = g_sel_src[i*3+1], sz = g_sel_src[i*3+2];
        float rx = g_sel_ref[i*3+0], ry = g_sel_ref[i*3+1], rz = g_sel_ref[i*3+2];
        float ax = R0*sx + R1*sy + R2*sz + t0;
        float ay = R3*sx + R4*sy + R5*sz + t1;
        float az = R6*sx + R7*sy + R8*sz + t2;
        float dx = rx - ax, dy = ry - ay, dz = rz - az;
        if (dx*dx + dy*dy + dz*dz < 0.01f) c++;
    }
    rc_[t] = c;
    __syncthreads();
    for (int off = 64; off; off >>= 1) {
        if (t < off) rc_[t] += rc_[t + off];
        __syncthreads();
    }
    if (t == 0) {
        int cnt = (g_pc[p] >= 3) ? rc_[0] : -1;
        int key = ((cnt + 1) << 16) | (NB - 1 - p);   // max count, tie -> smaller p
        atomicMax(&g_best_key, key);
    }
}

// ---------------- k5: 5 weighted-Procrustes refine iterations ----------------
__global__ void __launch_bounds__(256)
k5_refine(float* __restrict__ out)
{
    __shared__ float red[256 * 16];
    __shared__ float Tr[9], Tt[3];
    int t = threadIdx.x;
    if (t == 0) {
        int bb = NB - 1 - (g_best_key & 0xFFFF);
        for (int j = 0; j < 9; j++) Tr[j] = g_localT[bb*12 + j];
        for (int j = 0; j < 3; j++) Tt[j] = g_localT[bb*12 + 9 + j];
    }
    __syncthreads();

    for (int it = 0; it < 5; it++) {
        float P[16];
        for (int j = 0; j < 16; j++) P[j] = 0.0f;
        for (int i = t; i < CORR_LIM; i += 256) {
            float sv = g_sel_score[i];
            if (sv <= 0.0f) continue;
            float sx = g_sel_src[i*3+0], sy = g_sel_src[i*3+1], sz = g_sel_src[i*3+2];
            float rx = g_sel_ref[i*3+0], ry = g_sel_ref[i*3+1], rz = g_sel_ref[i*3+2];
            float ax = Tr[0]*sx + Tr[1]*sy + Tr[2]*sz + Tt[0];
            float ay = Tr[3]*sx + Tr[4]*sy + Tr[5]*sz + Tt[1];
            float az = Tr[6]*sx + Tr[7]*sy + Tr[8]*sz + Tt[2];
            float dx = rx - ax, dy = ry - ay, dz = rz - az;
            if (dx*dx + dy*dy + dz*dz < 0.01f) {
                P[0] += sv;
                P[1] += sv*sx; P[2] += sv*sy; P[3] += sv*sz;
                P[4] += sv*rx; P[5] += sv*ry; P[6] += sv*rz;
                P[7]  += sv*sx*rx; P[8]  += sv*sx*ry; P[9]  += sv*sx*rz;
                P[10] += sv*sy*rx; P[11] += sv*sy*ry; P[12] += sv*sy*rz;
                P[13] += sv*sz*rx; P[14] += sv*sz*ry; P[15] += sv*sz*rz;
            }
        }
        for (int j = 0; j < 16; j++) red[t*16 + j] = P[j];
        __syncthreads();
        for (int off = 128; off; off >>= 1) {
            if (t < off)
                for (int j = 0; j < 16; j++) red[t*16 + j] += red[(t + off)*16 + j];
            __syncthreads();
        }
        if (t == 0) {
            float Pf[16];
            for (int j = 0; j < 16; j++) Pf[j] = red[j];
            float R[9], tv[3];
            solveTf(Pf, R, tv);
            for (int j = 0; j < 9; j++) Tr[j] = R[j];
            for (int j = 0; j < 3; j++) Tt[j] = tv[j];
        }
        __syncthreads();
    }

    if (t == 0) {
        out[0]  = Tr[0]; out[1]  = Tr[1]; out[2]  = Tr[2]; out[3]  = Tt[0];
        out[4]  = Tr[3]; out[5]  = Tr[4]; out[6]  = Tr[5]; out[7]  = Tt[1];
        out[8]  = Tr[6]; out[9]  = Tr[7]; out[10] = Tr[8]; out[11] = Tt[2];
        out[12] = 0.0f; out[13] = 0.0f; out[14] = 0.0f; out[15] = 1.0f;
    }
}

// ---------------- launch ----------------
extern "C" void kernel_launch(void* const* d_in, const int* in_sizes, int n_in,
                              void* d_out, int out_size)
{
    const float* score = 0;
    const float* refp = 0;  const float* srcp = 0;
    const void*  refm = 0;  const void*  srcm = 0;
    for (int i = 0; i < n_in; i++) {
        int sz = in_sizes[i];
        if (sz == NB * NN * NN) {
            score = (const float*)d_in[i];
        } else if (sz == NB * NN * 3) {
            if (!refp) refp = (const float*)d_in[i];
            else       srcp = (const float*)d_in[i];
        } else if (sz == NB * NN) {
            if (!refm) refm = d_in[i];
            else       srcm = d_in[i];
        }
    }
    float* out = (float*)d_out;

    k_detect<<<2, 256>>>((const unsigned char*)refm, (const unsigned char*)srcm);
    k_norm_init<<<(NB * NN + 255) / 256, 256>>>(refm, srcm);
    k1_batch<<<NB, 256>>>(score, refp, srcp);
    k2_select<<<1, 1024>>>();
    k3_gather<<<(CAND_CAP + 255) / 256, 256>>>(refp, srcp);
    k4_counts<<<NB, 128>>>();
    k5_refine<<<1, 256>>>(out);
}